// round 17
// baseline (speedup 1.0000x reference)
#include <cuda_runtime.h>

// MeshGCN 2-layer GCN, N=100000, FEAT=16, E=3.2M.
// out_l[d] = dinv[d] * ( hs_l[d] + sum_{(s,d) in E} hs_l[s] ) + b_l
//   hs_l = (in_l @ W_l) * dinv,  dinv = rsqrt(deg_in + 1)
// Bucket adjacency (96 slots/node), one-pass build (4 edges/thread).
// Aggregation geometry: 16 lanes per node (one float column each, 64B record),
// 2 nodes per warp -> each gather LDG touches 2 cache lines (1.0 + 2.07 cyc)
// for 2 edges = ~1.54 cyc/edge, below both the 4-line octet scheme (1.8) and
// the LSU-bound 1-line scheme (1.82+). Double-buffered features; fused
// epilogues; 5 launches.

#define NMAX 100000
#define F 16
#define SLOTS 96
#define SPILLMAX 8192

__device__ int    g_cnt[NMAX];          // zero at entry (.bss first, cleared by agg_out)
__device__ int    g_adj[NMAX * SLOTS];
__device__ int    g_spill_cnt;
__device__ int    g_spill[SPILLMAX * 2];
__device__ __align__(128) float g_hsA[NMAX * 16];   // layer-1 features, 64B/node
__device__ __align__(128) float g_hsB[NMAX * 16];   // layer-2 features

// ---------------- tiny init: spill counter only ----------------
__global__ void k_init() {
    if (threadIdx.x == 0) g_spill_cnt = 0;
}

// ---------------- one-pass bucket build (4 edges/thread) ----------------
__device__ __forceinline__ void place_edge(int s, int d) {
    int p = atomicAdd(&g_cnt[d], 1);
    if (p < SLOTS) {
        g_adj[(size_t)d * SLOTS + p] = s;
    } else {
        int sp = atomicAdd(&g_spill_cnt, 1);
        if (sp < SPILLMAX) { g_spill[2 * sp] = s; g_spill[2 * sp + 1] = d; }
    }
}

__global__ __launch_bounds__(256) void k_bucket(const int* __restrict__ src,
                                                const int* __restrict__ dst, int E) {
    int t = blockIdx.x * 256 + threadIdx.x;
    int e = t * 4;
    if (e + 4 <= E) {
        int4 s4 = *reinterpret_cast<const int4*>(src + e);
        int4 d4 = *reinterpret_cast<const int4*>(dst + e);
        place_edge(s4.x, d4.x);
        place_edge(s4.y, d4.y);
        place_edge(s4.z, d4.z);
        place_edge(s4.w, d4.w);
    } else {
        for (; e < E; e++) place_edge(src[e], dst[e]);
    }
}

// ---------------- dense: hsA = (x @ W1) * dinv ----------------
__global__ __launch_bounds__(256) void k_pre1(const float* __restrict__ x,
                                              const float* __restrict__ W, int n) {
    __shared__ float sW[256];
    int tid = threadIdx.x;
    sW[tid] = W[tid];
    __syncthreads();
    int i = blockIdx.x * 256 + tid;
    if (i >= n) return;

    const float4* xp = reinterpret_cast<const float4*>(x) + (size_t)i * 4;
    float xr[16];
#pragma unroll
    for (int c = 0; c < 4; c++) {
        float4 t = xp[c];
        xr[c * 4 + 0] = t.x; xr[c * 4 + 1] = t.y;
        xr[c * 4 + 2] = t.z; xr[c * 4 + 3] = t.w;
    }
    float acc[16];
#pragma unroll
    for (int j = 0; j < 16; j++) acc[j] = 0.0f;
#pragma unroll
    for (int k = 0; k < 16; k++) {
        float xk = xr[k];
#pragma unroll
        for (int j = 0; j < 16; j++) acc[j] += xk * sW[k * 16 + j];
    }
    float dv = rsqrtf((float)(g_cnt[i] + 1));
    float4* op = reinterpret_cast<float4*>(g_hsA) + (size_t)i * 4;
#pragma unroll
    for (int c = 0; c < 4; c++) {
        float4 o;
        o.x = acc[c * 4 + 0] * dv; o.y = acc[c * 4 + 1] * dv;
        o.z = acc[c * 4 + 2] * dv; o.w = acc[c * 4 + 3] * dv;
        op[c] = o;
    }
}

// ---------------- gather core: 16 lanes/node, one float column per lane -----
// acc = hs[node*16+o] + sum_{neighbors s} hs[s*16+o]
__device__ __forceinline__ float gather_node(const float* __restrict__ hsf,
                                             int node, int o, unsigned hmask,
                                             int raw) {
    int len = raw < SLOTS ? raw : SLOTS;
    const int* row = &g_adj[(size_t)node * SLOTS];

    float acc0 = hsf[(size_t)node * 16 + o];   // self-loop seed
    float acc1 = 0.0f;

    int j = 0;
    for (; j + 16 <= len; j += 16) {           // full batches: 16 idx / half-warp
        int a = __ldg(&row[j + o]);            // 64B coalesced per half
        int s;
        float v0, v1, v2, v3, v4, v5, v6, v7;
        s = __shfl_sync(hmask, a,  0, 16); v0 = __ldg(&hsf[(size_t)s * 16 + o]);
        s = __shfl_sync(hmask, a,  1, 16); v1 = __ldg(&hsf[(size_t)s * 16 + o]);
        s = __shfl_sync(hmask, a,  2, 16); v2 = __ldg(&hsf[(size_t)s * 16 + o]);
        s = __shfl_sync(hmask, a,  3, 16); v3 = __ldg(&hsf[(size_t)s * 16 + o]);
        s = __shfl_sync(hmask, a,  4, 16); v4 = __ldg(&hsf[(size_t)s * 16 + o]);
        s = __shfl_sync(hmask, a,  5, 16); v5 = __ldg(&hsf[(size_t)s * 16 + o]);
        s = __shfl_sync(hmask, a,  6, 16); v6 = __ldg(&hsf[(size_t)s * 16 + o]);
        s = __shfl_sync(hmask, a,  7, 16); v7 = __ldg(&hsf[(size_t)s * 16 + o]);
        acc0 += v0; acc1 += v1; acc0 += v2; acc1 += v3;
        acc0 += v4; acc1 += v5; acc0 += v6; acc1 += v7;
        s = __shfl_sync(hmask, a,  8, 16); v0 = __ldg(&hsf[(size_t)s * 16 + o]);
        s = __shfl_sync(hmask, a,  9, 16); v1 = __ldg(&hsf[(size_t)s * 16 + o]);
        s = __shfl_sync(hmask, a, 10, 16); v2 = __ldg(&hsf[(size_t)s * 16 + o]);
        s = __shfl_sync(hmask, a, 11, 16); v3 = __ldg(&hsf[(size_t)s * 16 + o]);
        s = __shfl_sync(hmask, a, 12, 16); v4 = __ldg(&hsf[(size_t)s * 16 + o]);
        s = __shfl_sync(hmask, a, 13, 16); v5 = __ldg(&hsf[(size_t)s * 16 + o]);
        s = __shfl_sync(hmask, a, 14, 16); v6 = __ldg(&hsf[(size_t)s * 16 + o]);
        s = __shfl_sync(hmask, a, 15, 16); v7 = __ldg(&hsf[(size_t)s * 16 + o]);
        acc0 += v0; acc1 += v1; acc0 += v2; acc1 += v3;
        acc0 += v4; acc1 += v5; acc0 += v6; acc1 += v7;
    }
    if (j + 8 <= len) {                        // one half-batch
        int a = __ldg(&row[j + (o & 7)]);      // 8 idx, duplicated x2 per half
        int s;
        float v0, v1, v2, v3, v4, v5, v6, v7;
        s = __shfl_sync(hmask, a, 0, 16); v0 = __ldg(&hsf[(size_t)s * 16 + o]);
        s = __shfl_sync(hmask, a, 1, 16); v1 = __ldg(&hsf[(size_t)s * 16 + o]);
        s = __shfl_sync(hmask, a, 2, 16); v2 = __ldg(&hsf[(size_t)s * 16 + o]);
        s = __shfl_sync(hmask, a, 3, 16); v3 = __ldg(&hsf[(size_t)s * 16 + o]);
        s = __shfl_sync(hmask, a, 4, 16); v4 = __ldg(&hsf[(size_t)s * 16 + o]);
        s = __shfl_sync(hmask, a, 5, 16); v5 = __ldg(&hsf[(size_t)s * 16 + o]);
        s = __shfl_sync(hmask, a, 6, 16); v6 = __ldg(&hsf[(size_t)s * 16 + o]);
        s = __shfl_sync(hmask, a, 7, 16); v7 = __ldg(&hsf[(size_t)s * 16 + o]);
        acc0 += v0; acc1 += v1; acc0 += v2; acc1 += v3;
        acc0 += v4; acc1 += v5; acc0 += v6; acc1 += v7;
        j += 8;
    }
    for (; j < len; j++) {                     // scalar tail (<8 iters)
        int s = __ldg(&row[j]);                // uniform per half: 1 line
        acc0 += __ldg(&hsf[(size_t)s * 16 + o]);
    }

    if (raw > SLOTS) {                         // spill fold-in (normally dead)
        int m = g_spill_cnt;
        if (m > SPILLMAX) m = SPILLMAX;
        for (int i = 0; i < m; i++) {
            if (g_spill[2 * i + 1] == node)
                acc0 += __ldg(&hsf[(size_t)g_spill[2 * i] * 16 + o]);
        }
    }
    return acc0 + acc1;
}

// ---- agg_mid: gather hsA; y=relu(dinv*acc+b1); hsB=(y@W2)*dinv --------------
__global__ __launch_bounds__(256) void k_agg_mid(const float* __restrict__ W2,
                                                 const float* __restrict__ b1, int n) {
    __shared__ float sW[256];
    sW[threadIdx.x] = W2[threadIdx.x];
    __syncthreads();

    int lane  = threadIdx.x & 31;
    int o     = lane & 15;                        // feature column (0..15)
    unsigned hmask = 0xffffu << (lane & 16);      // this half-warp's lanes
    int node  = blockIdx.x * 16 + (threadIdx.x >> 4);
    if (node >= n) return;

    int raw = g_cnt[node];
    float acc = gather_node(g_hsA, node, o, hmask, raw);

    float dv = rsqrtf((float)(raw + 1));
    float y = acc * dv + __ldg(&b1[o]);
    y = y > 0.0f ? y : 0.0f;

    // h[o] = sum_k y[k] * W2[k][o]; y spread 1-per-lane across the half-warp
    float h = 0.0f;
#pragma unroll
    for (int k = 0; k < 16; k++) {
        float yk = __shfl_sync(hmask, y, k, 16);
        h += yk * sW[k * 16 + o];
    }
    g_hsB[(size_t)node * 16 + o] = h * dv;
}

// ---- agg_out: gather hsB; out = dinv*acc + b2 ; clear g_cnt -----------------
__global__ __launch_bounds__(256) void k_agg_out(const float* __restrict__ b2,
                                                 float* __restrict__ out, int n) {
    int lane  = threadIdx.x & 31;
    int o     = lane & 15;
    unsigned hmask = 0xffffu << (lane & 16);
    int node  = blockIdx.x * 16 + (threadIdx.x >> 4);
    if (node >= n) return;

    int raw = g_cnt[node];
    float acc = gather_node(g_hsB, node, o, hmask, raw);

    float dv = rsqrtf((float)(raw + 1));
    out[(size_t)node * 16 + o] = acc * dv + __ldg(&b2[o]);

    if (o == 0) g_cnt[node] = 0;    // restore invariant for the next call
}

extern "C" void kernel_launch(void* const* d_in, const int* in_sizes, int n_in,
                              void* d_out, int out_size) {
    const float* x  = (const float*)d_in[0];
    const int*   ei = (const int*)  d_in[1];
    const float* W1 = (const float*)d_in[2];
    const float* b1 = (const float*)d_in[3];
    const float* W2 = (const float*)d_in[4];
    const float* b2 = (const float*)d_in[5];
    float* out = (float*)d_out;

    int E = in_sizes[1] / 2;
    int n = in_sizes[0] / F;
    const int* src = ei;
    const int* dst = ei + E;

    int nb_n = (n + 255) / 256;
    int nb_e = (E / 4 + 255) / 256;   // 4 edges per thread
    int nb_a = (n + 15) / 16;         // 16 nodes per 256-thread block

    k_init    <<<1,    32>>>();
    k_bucket  <<<nb_e, 256>>>(src, dst, E);
    k_pre1    <<<nb_n, 256>>>(x, W1, n);
    k_agg_mid <<<nb_a, 256>>>(W2, b1, n);
    k_agg_out <<<nb_a, 256>>>(b2, out, n);
}